// round 2
// baseline (speedup 1.0000x reference)
#include <cuda_runtime.h>

// Problem constants (fixed by the reference)
#define B_     4
#define N_     4096
#define E_     128
#define CACHE_ 32
#define NK_    4
#define CE_    32      // E / NK
#define CP_    16      // channel pairs per lane
#define M_     128     // N / CACHE
#define BNE_   (B_*N_*E_)

// Inter-layer scratch (device globals: no allocation in kernel_launch)
__device__ float g_x [BNE_];
__device__ float g_xa[BNE_];

typedef unsigned long long u64;

__device__ __forceinline__ float tanh_fast(float x) {
    float y;
    asm("tanh.approx.f32 %0, %1;" : "=f"(y) : "f"(x));
    return y;
}
__device__ __forceinline__ u64 pk(float lo, float hi) {
    u64 r; asm("mov.b64 %0, {%1, %2};" : "=l"(r) : "f"(lo), "f"(hi)); return r;
}
__device__ __forceinline__ void upk(u64 x, float& lo, float& hi) {
    asm("mov.b64 {%0, %1}, %2;" : "=f"(lo), "=f"(hi) : "l"(x));
}
__device__ __forceinline__ u64 fma2(u64 a, u64 b, u64 c) {
    u64 d; asm("fma.rn.f32x2 %0, %1, %2, %3;" : "=l"(d) : "l"(a), "l"(b), "l"(c)); return d;
}
__device__ __forceinline__ u64 mul2(u64 a, u64 b) {
    u64 d; asm("mul.rn.f32x2 %0, %1, %2;" : "=l"(d) : "l"(a), "l"(b)); return d;
}
__device__ __forceinline__ u64 add2(u64 a, u64 b) {
    u64 d; asm("add.rn.f32x2 %0, %1, %2;" : "=l"(d) : "l"(a), "l"(b)); return d;
}

// One warp per (b, g, n) unit. lane = row-in-group, 16 packed channel-pairs
// in registers. Carries u = xi/2, v = xa/2 (T = u + sim*u_j is one FFMA2).
// Running dots (true scale): Ax=dot(xi,Wi), Bx=dot(xi,Wj), Aa, Ba likewise.
__global__ void __launch_bounds__(32, 14)
ncn_layer(const float* __restrict__ X, const float* __restrict__ XA,
          const float* __restrict__ W,        // 256 floats: Wi[4][32], Wj[4][32]
          float* __restrict__ YX, float* __restrict__ YA,
          int s)                               // group-index stride (0 or 1)
{
    __shared__ float tile[CACHE_][CACHE_ + 1];
    __shared__ u64 sWi[CP_];
    __shared__ u64 sWj[CP_];

    const int lane = threadIdx.x;
    const int blk  = blockIdx.x;               // 0 .. 2047
    const int n    = blk & (NK_ - 1);
    const int g    = (blk >> 2) & (M_ - 1);
    const int b    = blk >> 9;

    if (lane < CP_) {
        sWi[lane] = pk(W[       n * CE_ + 2 * lane], W[       n * CE_ + 2 * lane + 1]);
        sWj[lane] = pk(W[E_ +   n * CE_ + 2 * lane], W[E_ +   n * CE_ + 2 * lane + 1]);
    }

    const long long chanBase = (long long)n * CE_ + lane;
    const long long bBase    = (long long)b * N_ * E_;

    u64 u2[CP_], v2[CP_];

    // ---- gather xi tile (coalesced per row, transpose through smem) ----
    #pragma unroll
    for (int r = 0; r < CACHE_; ++r) {
        int row = ((g + r * s) & (M_ - 1)) * CACHE_ + r;
        tile[r][lane] = X[bBase + (long long)row * E_ + chanBase];
    }
    __syncwarp();
    #pragma unroll
    for (int c = 0; c < CP_; ++c)
        u2[c] = pk(0.5f * tile[lane][2 * c], 0.5f * tile[lane][2 * c + 1]);
    __syncwarp();

    // ---- gather xa tile ----
    #pragma unroll
    for (int r = 0; r < CACHE_; ++r) {
        int row = ((g + r * s) & (M_ - 1)) * CACHE_ + r;
        tile[r][lane] = XA[bBase + (long long)row * E_ + chanBase];
    }
    __syncwarp();
    #pragma unroll
    for (int c = 0; c < CP_; ++c)
        v2[c] = pk(0.5f * tile[lane][2 * c], 0.5f * tile[lane][2 * c + 1]);

    const u64 K09  = pk(0.9f,  0.9f);
    const u64 K01  = pk(0.1f,  0.1f);
    const u64 K005 = pk(0.05f, 0.05f);
    const u64 Z    = pk(0.f, 0.f);

    // ---- initial running dots (true scale = 2 * half-scale packed dot) ----
    float Ax, Bx, Aa, Ba;
    {
        u64 ax = Z, bx = Z, aa = Z, ba = Z;
        #pragma unroll
        for (int c = 0; c < CP_; ++c) {
            u64 wi = sWi[c], wj = sWj[c];
            ax = fma2(u2[c], wi, ax);
            bx = fma2(u2[c], wj, bx);
            aa = fma2(v2[c], wi, aa);
            ba = fma2(v2[c], wj, ba);
        }
        float l, h;
        upk(ax, l, h); Ax = 2.f * (l + h);
        upk(bx, l, h); Bx = 2.f * (l + h);
        upk(aa, l, h); Aa = 2.f * (l + h);
        upk(ba, l, h); Ba = 2.f * (l + h);
    }

    // ---- 32-step recurrence ----
    #pragma unroll 1
    for (int j = 0; j < CACHE_; ++j) {
        float sim = Ax + __shfl_sync(0xffffffffu, Bx, j);
        u64 sim2 = pk(sim, sim);
        u64 SFa = Z, SFb = Z, DFa = Z, DFb = Z;
        #pragma unroll
        for (int c = 0; c < CP_; ++c) {
            u64 uj = __shfl_sync(0xffffffffu, u2[c], j);   // pre-update row j
            u64 T  = fma2(sim2, uj, u2[c]);                // 0.5*xi + 0.5*sim*xj
            float t0, t1; upk(T, t0, t1);
            u64 F = pk(tanh_fast(t0), tanh_fast(t1));
            if (c & 1) { SFb = fma2(F, sWi[c], SFb); DFb = fma2(F, sWj[c], DFb); }
            else       { SFa = fma2(F, sWi[c], SFa); DFa = fma2(F, sWj[c], DFa); }
            v2[c] = fma2(v2[c], K09, mul2(F, K005));       // xa' = .9 xa + .1 F
            u2[c] = fma2(u2[c], K09, mul2(v2[c], K01));    // xi' = .9 xi + .1 xa'
        }
        float l, h, SF, DF;
        { u64 t = add2(SFa, SFb); upk(t, l, h); SF = l + h; }
        { u64 t = add2(DFa, DFb); upk(t, l, h); DF = l + h; }
        Aa = fmaf(0.1f, SF, 0.9f * Aa);
        Ax = fmaf(0.1f, Aa, 0.9f * Ax);
        Ba = fmaf(0.1f, DF, 0.9f * Ba);
        Bx = fmaf(0.1f, Ba, 0.9f * Bx);
    }

    // ---- scatter yi (scale back to true values) ----
    __syncwarp();
    #pragma unroll
    for (int c = 0; c < CP_; ++c) {
        float l, h; upk(u2[c], l, h);
        tile[lane][2 * c] = 2.f * l; tile[lane][2 * c + 1] = 2.f * h;
    }
    __syncwarp();
    #pragma unroll
    for (int r = 0; r < CACHE_; ++r) {
        int row = ((g + r * s) & (M_ - 1)) * CACHE_ + r;
        YX[bBase + (long long)row * E_ + chanBase] = tile[r][lane];
    }
    __syncwarp();

    // ---- scatter ya ----
    #pragma unroll
    for (int c = 0; c < CP_; ++c) {
        float l, h; upk(v2[c], l, h);
        tile[lane][2 * c] = 2.f * l; tile[lane][2 * c + 1] = 2.f * h;
    }
    __syncwarp();
    #pragma unroll
    for (int r = 0; r < CACHE_; ++r) {
        int row = ((g + r * s) & (M_ - 1)) * CACHE_ + r;
        YA[bBase + (long long)row * E_ + chanBase] = tile[r][lane];
    }
}

extern "C" void kernel_launch(void* const* d_in, const int* in_sizes, int n_in,
                              void* d_out, int out_size) {
    const float* x  = (const float*)d_in[0];
    const float* xa = (const float*)d_in[1];
    const float* W  = (const float*)d_in[2];
    float* out = (float*)d_out;

    float *gx = nullptr, *gxa = nullptr;
    cudaGetSymbolAddress((void**)&gx,  g_x);
    cudaGetSymbolAddress((void**)&gxa, g_xa);

    dim3 grid(B_ * M_ * NK_);   // 2048 one-warp blocks
    dim3 block(32);

    // Layer 0: stage shift s = 0 (contiguous groups)
    ncn_layer<<<grid, block>>>(x, xa, W, gx, gxa, 0);
    // Layer 1: stage shift s = 1 (block = (g + o) % m), writes final output
    ncn_layer<<<grid, block>>>(gx, gxa, W + 2 * E_, out, out + BNE_, 1);
}

// round 3
// speedup vs baseline: 1.1055x; 1.1055x over previous
#include <cuda_runtime.h>

// Problem constants (fixed by the reference)
#define B_     4
#define N_     4096
#define E_     128
#define CACHE_ 32
#define NK_    4
#define CE_    32      // channels per unit (E / NK)
#define M_     128     // N / CACHE
#define BNE_   (B_*N_*E_)
#define KP_    8       // channel pairs per warp (16 channels)

// Inter-layer scratch (device globals: no allocation in kernel_launch)
__device__ float g_x [BNE_];
__device__ float g_xa[BNE_];

typedef unsigned long long u64;

__device__ __forceinline__ float tanh_fast(float x) {
    float y;
    asm("tanh.approx.f32 %0, %1;" : "=f"(y) : "f"(x));
    return y;
}
__device__ __forceinline__ u64 pk(float lo, float hi) {
    u64 r; asm("mov.b64 %0, {%1, %2};" : "=l"(r) : "f"(lo), "f"(hi)); return r;
}
__device__ __forceinline__ void upk(u64 x, float& lo, float& hi) {
    asm("mov.b64 {%0, %1}, %2;" : "=f"(lo), "=f"(hi) : "l"(x));
}
__device__ __forceinline__ u64 fma2(u64 a, u64 b, u64 c) {
    u64 d; asm("fma.rn.f32x2 %0, %1, %2, %3;" : "=l"(d) : "l"(a), "l"(b), "l"(c)); return d;
}
__device__ __forceinline__ u64 mul2(u64 a, u64 b) {
    u64 d; asm("mul.rn.f32x2 %0, %1, %2;" : "=l"(d) : "l"(a), "l"(b)); return d;
}
__device__ __forceinline__ u64 add2(u64 a, u64 b) {
    u64 d; asm("add.rn.f32x2 %0, %1, %2;" : "=l"(d) : "l"(a), "l"(b)); return d;
}

// 2 warps per (b,g,n) unit. lane = row-in-group. Warp w owns channels
// [w*16, w*16+16) as 8 packed f32 pairs. Rescaled state:
//   u2 = (xi/2) / 0.9^j,  v2 = (xa/2) / 0.9^j
// Per-step updates: v' = v + c_j*F (1 fma), u' = u + 0.1*v' (1 fma),
//   T = 0.9^j * (u + sim*u_j) (fma+mul).
// Full running dots (true scale, identical in both warps, packed):
//   A2 = (Aa=dot(xa,Wi), Ba=dot(xa,Wj)), X2 = (Ax=dot(xi,Wi), Bx=dot(xi,Wj)).
// Partial dot(F,W) summed across the 2 warps via double-buffered smem + 1 bar.
__global__ void __launch_bounds__(64, 12)
ncn_layer(const float* __restrict__ X, const float* __restrict__ XA,
          const float* __restrict__ W,         // 256 floats: Wi[4][32], Wj[4][32]
          float* __restrict__ YX, float* __restrict__ YA,
          int s)                                // group-index stride (0 or 1)
{
    __shared__ float tile[CACHE_][CACHE_ + 1];
    __shared__ float2 ebuf[2][2][CACHE_];       // [parity][warp][lane]
    __shared__ u64 sWi[16], sWj[16];            // packed weight pairs (all 32 ch)

    const int t    = threadIdx.x;
    const int w    = t >> 5;                    // warp in block (0/1)
    const int lane = t & 31;                    // row-in-group
    const int blk  = blockIdx.x;                // 0 .. 2047
    const int n    = blk & (NK_ - 1);
    const int g    = (blk >> 2) & (M_ - 1);
    const int b    = blk >> 9;

    if (t < 16) {
        sWi[t] = pk(W[       n * CE_ + 2 * t], W[       n * CE_ + 2 * t + 1]);
        sWj[t] = pk(W[E_ +   n * CE_ + 2 * t], W[E_ +   n * CE_ + 2 * t + 1]);
    }

    const long long bBase    = (long long)b * N_ * E_;
    const long long chanBase = (long long)n * CE_ + lane;
    const int cw = w * 16;                      // this warp's first channel

    u64 u2[KP_], v2[KP_];

    // ---- gather xi tile: warp w loads rows [w*16, w*16+16), coalesced ----
    #pragma unroll
    for (int r = 0; r < 16; ++r) {
        int rr  = cw + r;
        int row = ((g + rr * s) & (M_ - 1)) * CACHE_ + rr;
        tile[rr][lane] = X[bBase + (long long)row * E_ + chanBase];
    }
    __syncthreads();
    #pragma unroll
    for (int k = 0; k < KP_; ++k)
        u2[k] = pk(0.5f * tile[lane][cw + 2 * k], 0.5f * tile[lane][cw + 2 * k + 1]);
    __syncthreads();

    // ---- gather xa tile ----
    #pragma unroll
    for (int r = 0; r < 16; ++r) {
        int rr  = cw + r;
        int row = ((g + rr * s) & (M_ - 1)) * CACHE_ + rr;
        tile[rr][lane] = XA[bBase + (long long)row * E_ + chanBase];
    }
    __syncthreads();
    #pragma unroll
    for (int k = 0; k < KP_; ++k)
        v2[k] = pk(0.5f * tile[lane][cw + 2 * k], 0.5f * tile[lane][cw + 2 * k + 1]);

    const u64 K09 = pk(0.9f, 0.9f);
    const u64 K01 = pk(0.1f, 0.1f);
    const u64 Z   = pk(0.f, 0.f);

    // ---- initial partial dots (true scale = 2 * half-scale dot) ----
    float Axp, Bxp, Aap, Bap;
    {
        u64 ax = Z, bx = Z, aa = Z, ba = Z;
        #pragma unroll
        for (int k = 0; k < KP_; ++k) {
            u64 wi = sWi[w * KP_ + k], wj = sWj[w * KP_ + k];
            ax = fma2(u2[k], wi, ax);
            bx = fma2(u2[k], wj, bx);
            aa = fma2(v2[k], wi, aa);
            ba = fma2(v2[k], wj, ba);
        }
        float l, h;
        upk(ax, l, h); Axp = 2.f * (l + h);
        upk(bx, l, h); Bxp = 2.f * (l + h);
        upk(aa, l, h); Aap = 2.f * (l + h);
        upk(ba, l, h); Bap = 2.f * (l + h);
    }
    // exchange partials (two rounds through ebuf[0])
    u64 X2, A2;  // (Ax,Bx), (Aa,Ba)
    ebuf[0][w][lane] = make_float2(Axp, Bxp);
    __syncthreads();
    {
        float2 p0 = ebuf[0][0][lane], p1 = ebuf[0][1][lane];
        X2 = pk(p0.x + p1.x, p0.y + p1.y);
    }
    __syncthreads();
    ebuf[0][w][lane] = make_float2(Aap, Bap);
    __syncthreads();
    {
        float2 p0 = ebuf[0][0][lane], p1 = ebuf[0][1][lane];
        A2 = pk(p0.x + p1.x, p0.y + p1.y);
    }
    __syncthreads();   // protect ebuf[0] before step-0 writes

    float sc = 1.0f;                  // 0.9^j
    float cj = 0.05f / 0.9f;          // 0.05 / 0.9^(j+1)

    // ---- 32-step recurrence ----
    #pragma unroll 1
    for (int j = 0; j < CACHE_; ++j) {
        float Ax, Bx; upk(X2, Ax, Bx);
        float sim = Ax + __shfl_sync(0xffffffffu, Bx, j);
        u64 sim2 = pk(sim, sim);
        u64 s2   = pk(sc, sc);
        u64 c2   = pk(cj, cj);
        u64 SA = Z, SB = Z, DA = Z, DB = Z;
        #pragma unroll
        for (int k = 0; k < KP_; ++k) {
            u64 uj = __shfl_sync(0xffffffffu, u2[k], j);    // pre-update row j
            u64 T  = mul2(s2, fma2(sim2, uj, u2[k]));       // true-scale T
            float t0, t1; upk(T, t0, t1);
            u64 F = pk(tanh_fast(t0), tanh_fast(t1));
            u64 wi = sWi[w * KP_ + k], wj = sWj[w * KP_ + k];
            if (k & 1) { SB = fma2(F, wi, SB); DB = fma2(F, wj, DB); }
            else       { SA = fma2(F, wi, SA); DA = fma2(F, wj, DA); }
            v2[k] = fma2(c2,  F,     v2[k]);                // ~xa update
            u2[k] = fma2(K01, v2[k], u2[k]);                // ~xi update
        }
        float l, h, SFp, DFp;
        { u64 q = add2(SA, SB); upk(q, l, h); SFp = l + h; }
        { u64 q = add2(DA, DB); upk(q, l, h); DFp = l + h; }

        int p = j & 1;
        ebuf[p][w][lane] = make_float2(SFp, DFp);
        __syncthreads();
        float2 p0 = ebuf[p][0][lane], p1 = ebuf[p][1][lane];
        u64 S2 = pk(p0.x + p1.x, p0.y + p1.y);              // (SF, DF) totals

        A2 = fma2(A2, K09, mul2(S2, K01));                  // Aa,Ba update
        X2 = fma2(X2, K09, mul2(A2, K01));                  // Ax,Bx update
        sc *= 0.9f;
        cj *= (1.0f / 0.9f);
    }

    const float fscale = 2.0f * sc;   // undo half-scale and 0.9^32 rescale

    // ---- scatter yi ----
    __syncthreads();
    #pragma unroll
    for (int k = 0; k < KP_; ++k) {
        float l, h; upk(u2[k], l, h);
        tile[lane][cw + 2 * k]     = fscale * l;
        tile[lane][cw + 2 * k + 1] = fscale * h;
    }
    __syncthreads();
    #pragma unroll
    for (int r = 0; r < 16; ++r) {
        int rr  = cw + r;
        int row = ((g + rr * s) & (M_ - 1)) * CACHE_ + rr;
        YX[bBase + (long long)row * E_ + chanBase] = tile[rr][lane];
    }
    __syncthreads();

    // ---- scatter ya ----
    #pragma unroll
    for (int k = 0; k < KP_; ++k) {
        float l, h; upk(v2[k], l, h);
        tile[lane][cw + 2 * k]     = fscale * l;
        tile[lane][cw + 2 * k + 1] = fscale * h;
    }
    __syncthreads();
    #pragma unroll
    for (int r = 0; r < 16; ++r) {
        int rr  = cw + r;
        int row = ((g + rr * s) & (M_ - 1)) * CACHE_ + rr;
        YA[bBase + (long long)row * E_ + chanBase] = tile[rr][lane];
    }
}

extern "C" void kernel_launch(void* const* d_in, const int* in_sizes, int n_in,
                              void* d_out, int out_size) {
    const float* x  = (const float*)d_in[0];
    const float* xa = (const float*)d_in[1];
    const float* W  = (const float*)d_in[2];
    float* out = (float*)d_out;

    float *gx = nullptr, *gxa = nullptr;
    cudaGetSymbolAddress((void**)&gx,  g_x);
    cudaGetSymbolAddress((void**)&gxa, g_xa);

    dim3 grid(B_ * M_ * NK_);   // 2048 blocks
    dim3 block(64);             // 2 warps per unit

    // Layer 0: stage shift s = 0 (contiguous groups)
    ncn_layer<<<grid, block>>>(x, xa, W, gx, gxa, 0);
    // Layer 1: stage shift s = 1 (block = (g + o) % m), writes final output
    ncn_layer<<<grid, block>>>(gx, gxa, W + 2 * E_, out, out + BNE_, 1);
}